// round 12
// baseline (speedup 1.0000x reference)
#include <cuda_runtime.h>
#include <cuda_fp16.h>
#include <cstdint>
#include <cstddef>

#define DEVI __device__ __forceinline__

// ---------------- problem dims ----------------
constexpr int DB = 2, DN = 384, DO = 4, DC = 128, DK = 64;
constexpr int SPLITS = 6;                  // split-K over source points n
constexpr int N_PER_SPLIT = DN / SPLITS;   // 64 source points per CTA
constexpr int NITER = N_PER_SPLIT;         // 64 stages, K=64 each (one n per stage)
constexpr int STAGES = 4;
constexpr int MTILES = 3;                  // 384 / 128

constexpr int A_ROWF = 72;                 // A row stride in floats (64 + 8 pad)
constexpr int A_STAGE_F = 128 * A_ROWF;    // 9216 floats = 36864 B per stage
constexpr int X_STAGE_F = 128;             // one x row (512 B) per stage
constexpr int SMEM_FLOATS = STAGES * A_STAGE_F + STAGES * X_STAGE_F;
constexpr int SMEM_BYTES = SMEM_FLOATS * 4;   // 149504

// ---------------- static device scratch (no runtime allocation) ----------------
__device__ float g_Ypart[(size_t)SPLITS * DB * DN * DO * DC];  // [s][b][m][o][c] ~9.4 MB

// ---------------- PTX helpers ----------------
DEVI uint32_t smem_u32(const void* p) {
    uint32_t a;
    asm("{ .reg .u64 t; cvta.to.shared.u64 t, %1; cvt.u32.u64 %0, t; }" : "=r"(a) : "l"(p));
    return a;
}
DEVI void cp16(uint32_t dst, const void* src) {
    asm volatile("cp.async.cg.shared.global [%0], [%1], 16;" :: "r"(dst), "l"(src) : "memory");
}
DEVI void cp_commit() { asm volatile("cp.async.commit_group;" ::: "memory"); }
template <int N> DEVI void cp_wait() {
    asm volatile("cp.async.wait_group %0;" :: "n"(N) : "memory");
}
DEVI uint32_t pack_h2(float lo, float hi) {  // d = {lo half, hi half}
    uint32_t d;
    asm("cvt.rn.f16x2.f32 %0, %1, %2;" : "=r"(d) : "f"(hi), "f"(lo));
    return d;
}
DEVI uint32_t hmul2(uint32_t a, uint32_t b) {
    uint32_t d;
    asm("mul.rn.f16x2 %0, %1, %2;" : "=r"(d) : "r"(a), "r"(b));
    return d;
}
DEVI void mma_f16(float& c0, float& c1, float& c2, float& c3,
                  uint32_t a0, uint32_t a1, uint32_t a2, uint32_t a3,
                  uint32_t b0, uint32_t b1) {
    asm volatile(
        "mma.sync.aligned.m16n8k16.row.col.f32.f16.f16.f32 "
        "{%0,%1,%2,%3}, {%4,%5,%6,%7}, {%8,%9}, {%0,%1,%2,%3};"
        : "+f"(c0), "+f"(c1), "+f"(c2), "+f"(c3)
        : "r"(a0), "r"(a1), "r"(a2), "r"(a3), "r"(b0), "r"(b1));
}

// ---------------- GEMM: on-the-fly B operand, warp tile 32x64 ----------------
// CTA (256 thr, 8 warps in 4(M) x 2(N) grid):
//   Ypart[s][b][m0:m0+128][o][:] = KB_tile[128, 4096] @ B^T, with
//   B[c][n*64+k] = half(x[b,n,o,c]) * half(W_spatial[k,c]) generated in registers.
__global__ void __launch_bounds__(256, 1) sepconv_gemm(const float* __restrict__ KB,
                                                       const float* __restrict__ x,
                                                       const float* __restrict__ Ws) {
    extern __shared__ float sm[];  // [STAGES][A fp32 128x72] then [STAGES][x 128]

    const int tid = threadIdx.x;
    const int w = tid >> 5, lid = tid & 31;
    const int gid = lid >> 2, tig = lid & 3;
    const int wm = w >> 1, wn = w & 1;   // warp grid 4 (M) x 2 (N)

    const int cta = blockIdx.x;          // 0..143
    const int s  = cta % SPLITS;
    const int mt = (cta / SPLITS) % MTILES;
    const int bo = cta / (SPLITS * MTILES);
    const int b = bo >> 2, o = bo & 3;
    const int m0 = mt * 128;
    const int n0 = s * N_PER_SPLIT;

    // ---- loop-invariant W fragment registers ----
    // Wreg[ni][kk][j] = {W[k, c_ni], W[k+1, c_ni]} with k = kk*16 + 2*tig + 8*j
    uint32_t Wreg[8][4][2];
    #pragma unroll
    for (int ni = 0; ni < 8; ni++) {
        const int c = wn * 64 + ni * 8 + gid;
        #pragma unroll
        for (int kk = 0; kk < 4; kk++)
            #pragma unroll
            for (int j = 0; j < 2; j++) {
                const int k = kk * 16 + 2 * tig + 8 * j;
                Wreg[ni][kk][j] = pack_h2(Ws[k * DC + c], Ws[(k + 1) * DC + c]);
            }
    }

    // ---- A loaders: 2 threads per row, 32 floats each ----
    const int lrow = tid >> 1, lsub = tid & 1;
    const float* aSrc = KB + (size_t)b * ((size_t)DN * DN * DO * DK)
                           + (size_t)(m0 + lrow) * (DN * DO * DK)
                           + (size_t)n0 * (DO * DK) + (size_t)o * DK + lsub * 32;
    const float* xSrc = x + ((size_t)(b * DN + n0) * DO + o) * DC;  // +it*512 per stage
    const uint32_t smem0 = smem_u32(sm);
    const uint32_t aDst0 = smem0 + (uint32_t)lrow * (A_ROWF * 4) + (uint32_t)lsub * 128;
    const uint32_t xBase = smem0 + STAGES * A_STAGE_F * 4;

    auto load_stage = [&](int st) {
        const uint32_t so = (uint32_t)(st % STAGES) * (A_STAGE_F * 4);
        const float* src = aSrc + (size_t)st * (DO * DK);
        const uint32_t d = aDst0 + so;
        #pragma unroll
        for (int j = 0; j < 8; j++) cp16(d + j * 16, src + j * 4);
        if (tid < 32)
            cp16(xBase + (uint32_t)(st % STAGES) * 512 + (uint32_t)tid * 16,
                 xSrc + (size_t)st * (DO * DC) + tid * 4);
    };

    float acc[2][8][4];
    #pragma unroll
    for (int mi = 0; mi < 2; mi++)
        #pragma unroll
        for (int ni = 0; ni < 8; ni++)
            #pragma unroll
            for (int r = 0; r < 4; r++) acc[mi][ni][r] = 0.f;

    // ---- prologue ----
    #pragma unroll
    for (int st = 0; st < STAGES - 1; st++) { load_stage(st); cp_commit(); }

    // ---- mainloop: one source point n (K=64) per iteration ----
    for (int it = 0; it < NITER; it++) {
        cp_wait<STAGES - 2>();   // stage `it` resident
        __syncthreads();
        if (it + STAGES - 1 < NITER) load_stage(it + STAGES - 1);
        cp_commit();

        const float* As = sm + (it % STAGES) * A_STAGE_F;
        const float* xs = sm + STAGES * A_STAGE_F + (it % STAGES) * X_STAGE_F;

        // x broadcast values for this point, one per ni-column
        uint32_t xh2[8];
        #pragma unroll
        for (int ni = 0; ni < 8; ni++) {
            const float xv = xs[wn * 64 + ni * 8 + gid];
            xh2[ni] = pack_h2(xv, xv);
        }

        #pragma unroll
        for (int kk = 0; kk < 4; kk++) {   // K=16 chunks
            uint32_t a[2][4];
            #pragma unroll
            for (int mi = 0; mi < 2; mi++) {
                const float* ap = As + (wm * 32 + mi * 16 + gid) * A_ROWF + kk * 16 + 2 * tig;
                const float2 v00 = *(const float2*)(ap);
                const float2 v10 = *(const float2*)(ap + 8 * A_ROWF);
                const float2 v01 = *(const float2*)(ap + 8);
                const float2 v11 = *(const float2*)(ap + 8 * A_ROWF + 8);
                a[mi][0] = pack_h2(v00.x, v00.y);
                a[mi][1] = pack_h2(v10.x, v10.y);
                a[mi][2] = pack_h2(v01.x, v01.y);
                a[mi][3] = pack_h2(v11.x, v11.y);
            }
            #pragma unroll
            for (int ni = 0; ni < 8; ni++) {
                const uint32_t b0 = hmul2(xh2[ni], Wreg[ni][kk][0]);
                const uint32_t b1 = hmul2(xh2[ni], Wreg[ni][kk][1]);
                #pragma unroll
                for (int mi = 0; mi < 2; mi++)
                    mma_f16(acc[mi][ni][0], acc[mi][ni][1], acc[mi][ni][2], acc[mi][ni][3],
                            a[mi][0], a[mi][1], a[mi][2], a[mi][3], b0, b1);
            }
        }
    }

    // ---- epilogue: write partials ----
    #pragma unroll
    for (int mi = 0; mi < 2; mi++) {
        const int row = m0 + wm * 32 + mi * 16 + gid;
        float* y0 = g_Ypart + ((((size_t)s * DB + b) * DN + row) * DO + o) * DC;
        float* y1 = g_Ypart + ((((size_t)s * DB + b) * DN + row + 8) * DO + o) * DC;
        #pragma unroll
        for (int ni = 0; ni < 8; ni++) {
            const int col = wn * 64 + ni * 8 + 2 * tig;
            *(float2*)(y0 + col) = make_float2(acc[mi][ni][0], acc[mi][ni][1]);
            *(float2*)(y1 + col) = make_float2(acc[mi][ni][2], acc[mi][ni][3]);
        }
    }
}

// ---------------- fused: rot compute + split-K reduce + fiber rotation + bias ----------
// block = (128, 2); y==0 threads first compute rot[p][o][c] for this block's c into smem.
__global__ void __launch_bounds__(256) sepconv_reduce(const float* __restrict__ fkb,
                                                      const float* __restrict__ Wr,
                                                      const float* __restrict__ bias,
                                                      float* __restrict__ out) {
    __shared__ float fk_s[16 * DK];        // fkb[p][o][k], 4 KB
    __shared__ float rot_s[16 * DC];       // rot[p*4+o][c], 8 KB

    const int tid = threadIdx.y * DC + threadIdx.x;
    for (int i = tid; i < 16 * DK; i += 256) fk_s[i] = fkb[i];
    __syncthreads();

    const int c = threadIdx.x;
    if (threadIdx.y == 0) {
        float racc[16];
        #pragma unroll
        for (int po = 0; po < 16; po++) racc[po] = 0.f;
        #pragma unroll 8
        for (int k = 0; k < DK; k++) {
            const float wv = Wr[k * DC + c];
            #pragma unroll
            for (int po = 0; po < 16; po++) racc[po] += fk_s[po * DK + k] * wv;
        }
        #pragma unroll
        for (int po = 0; po < 16; po++) rot_s[po * DC + c] = racc[po];
    }
    __syncthreads();

    const int bm = blockIdx.x * 2 + threadIdx.y;  // 0..767
    const int b = bm / DN, m = bm % DN;

    float y[DO];
    #pragma unroll
    for (int o = 0; o < DO; o++) y[o] = 0.f;
    #pragma unroll
    for (int s = 0; s < SPLITS; s++) {
        const float* p = g_Ypart + (((size_t)s * DB + b) * DN + m) * DO * DC + c;
        #pragma unroll
        for (int o = 0; o < DO; o++) y[o] += p[o * DC];
    }
    const float bi = bias[c];
    #pragma unroll
    for (int p = 0; p < DO; p++) {
        float acc = bi;
        #pragma unroll
        for (int o = 0; o < DO; o++) acc += y[o] * rot_s[(p * 4 + o) * DC + c];
        out[(((size_t)b * DN + m) * DO + p) * DC + c] = acc;
    }
}

// ---------------- launcher ----------------
extern "C" void kernel_launch(void* const* d_in, const int* in_sizes, int n_in,
                              void* d_out, int out_size) {
    (void)in_sizes; (void)n_in; (void)out_size;
    const float* x    = (const float*)d_in[0];
    const float* KB   = (const float*)d_in[1];
    const float* fkb  = (const float*)d_in[2];
    const float* Ws   = (const float*)d_in[3];
    const float* Wr   = (const float*)d_in[4];
    const float* bias = (const float*)d_in[5];
    float* out = (float*)d_out;

    static bool attr_done = false;
    if (!attr_done) {
        cudaFuncSetAttribute(sepconv_gemm, cudaFuncAttributeMaxDynamicSharedMemorySize,
                             SMEM_BYTES);
        attr_done = true;
    }

    sepconv_gemm<<<SPLITS * MTILES * DB * DO, 256, SMEM_BYTES>>>(KB, x, Ws);
    sepconv_reduce<<<DB * DN / 2, dim3(DC, 2)>>>(fkb, Wr, bias, out);
}

// round 14
// speedup vs baseline: 1.0703x; 1.0703x over previous
#include <cuda_runtime.h>
#include <cuda_fp16.h>
#include <cstdint>
#include <cstddef>

#define DEVI __device__ __forceinline__

// ---------------- problem dims ----------------
constexpr int DB = 2, DN = 384, DO = 4, DC = 128, DK = 64;
constexpr int SPLITS = 6;                  // split-K over source points n
constexpr int N_PER_SPLIT = DN / SPLITS;   // 64 source points per CTA
constexpr int NITER = N_PER_SPLIT;         // 64 stages, K=64 each (one n per stage)
constexpr int STAGES = 4;
constexpr int MTILES = 3;                  // 384 / 128
constexpr int GEMM_CTAS = SPLITS * MTILES * DB * DO;  // 144

constexpr int A_ROWF = 72;                 // A row stride in floats (64 + 8 pad)
constexpr int A_STAGE_F = 128 * A_ROWF;    // 9216 floats = 36864 B per stage
constexpr int X_STAGE_F = 128;             // one x row (512 B) per stage
constexpr int SMEM_FLOATS = STAGES * A_STAGE_F + STAGES * X_STAGE_F;
constexpr int SMEM_BYTES = SMEM_FLOATS * 4;   // 149504

// ---------------- static device scratch (no runtime allocation) ----------------
__device__ float g_Ypart[(size_t)SPLITS * DB * DN * DO * DC];  // [s][b][m][o][c] ~9.4 MB
__device__ float g_rot[DO][DO][DC];                            // [p][o][c]

// ---------------- PTX helpers ----------------
DEVI uint32_t smem_u32(const void* p) {
    uint32_t a;
    asm("{ .reg .u64 t; cvta.to.shared.u64 t, %1; cvt.u32.u64 %0, t; }" : "=r"(a) : "l"(p));
    return a;
}
DEVI void cp16(uint32_t dst, const void* src) {
    asm volatile("cp.async.cg.shared.global [%0], [%1], 16;" :: "r"(dst), "l"(src) : "memory");
}
DEVI void cp_commit() { asm volatile("cp.async.commit_group;" ::: "memory"); }
template <int N> DEVI void cp_wait() {
    asm volatile("cp.async.wait_group %0;" :: "n"(N) : "memory");
}
DEVI uint32_t pack_h2(float lo, float hi) {  // d = {lo half, hi half}
    uint32_t d;
    asm("cvt.rn.f16x2.f32 %0, %1, %2;" : "=r"(d) : "f"(hi), "f"(lo));
    return d;
}
DEVI uint32_t hmul2(uint32_t a, uint32_t b) {
    uint32_t d;
    asm("mul.rn.f16x2 %0, %1, %2;" : "=r"(d) : "r"(a), "r"(b));
    return d;
}
DEVI void mma_f16(float& c0, float& c1, float& c2, float& c3,
                  uint32_t a0, uint32_t a1, uint32_t a2, uint32_t a3,
                  uint32_t b0, uint32_t b1) {
    asm volatile(
        "mma.sync.aligned.m16n8k16.row.col.f32.f16.f16.f32 "
        "{%0,%1,%2,%3}, {%4,%5,%6,%7}, {%8,%9}, {%0,%1,%2,%3};"
        : "+f"(c0), "+f"(c1), "+f"(c2), "+f"(c3)
        : "r"(a0), "r"(a1), "r"(a2), "r"(a3), "r"(b0), "r"(b1));
}

// ---------------- GEMM: on-the-fly B operand, warp tile 64x32 (2x4 grid) ----------------
// CTA (256 thr): Ypart[s][b][m0:m0+128][o][:] = KB_tile[128, 4096] @ B^T, with
//   B[c][n*64+k] = half(x[b,n,o,c]) * half(W_spatial[k,c]) generated in registers.
// CTA 144 (extra): computes g_rot = fkb @ W_rot instead (rides a free SM).
__global__ void __launch_bounds__(256, 1) sepconv_gemm(const float* __restrict__ KB,
                                                       const float* __restrict__ x,
                                                       const float* __restrict__ Ws,
                                                       const float* __restrict__ fkb,
                                                       const float* __restrict__ Wr) {
    extern __shared__ float sm[];  // [STAGES][A fp32 128x72] then [STAGES][x 128]

    const int tid = threadIdx.x;
    const int cta = blockIdx.x;          // 0..144

    if (cta == GEMM_CTAS) {
        // ---- rot CTA: rot[p][o][c] = sum_k fkb[p,o,k] * Wr[k,c] ----
        __shared__ float fk_s[16 * DK];   // 4 KB (fits in dynamic smem region)
        float* fks = sm;                  // reuse dynamic smem
        for (int i = tid; i < 16 * DK; i += 256) fks[i] = fkb[i];
        __syncthreads();
        const int c = tid & 127;
        const int ph = tid >> 7;          // 0..1 -> po groups of 8
        (void)fk_s;
        float racc[8];
        #pragma unroll
        for (int q = 0; q < 8; q++) racc[q] = 0.f;
        #pragma unroll 8
        for (int k = 0; k < DK; k++) {
            const float wv = Wr[k * DC + c];
            #pragma unroll
            for (int q = 0; q < 8; q++)
                racc[q] += fks[(ph * 8 + q) * DK + k] * wv;
        }
        #pragma unroll
        for (int q = 0; q < 8; q++) {
            const int po = ph * 8 + q;
            g_rot[po >> 2][po & 3][c] = racc[q];
        }
        return;
    }

    const int w = tid >> 5, lid = tid & 31;
    const int gid = lid >> 2, tig = lid & 3;
    const int wm = w >> 2, wn = w & 3;   // warp grid 2 (M) x 4 (N)

    const int s  = cta % SPLITS;
    const int mt = (cta / SPLITS) % MTILES;
    const int bo = cta / (SPLITS * MTILES);
    const int b = bo >> 2, o = bo & 3;
    const int m0 = mt * 128;
    const int n0 = s * N_PER_SPLIT;

    // ---- loop-invariant W fragment registers ----
    // Wreg[ni][kk][j] = {W[k, c_ni], W[k+1, c_ni]} with k = kk*16 + 2*tig + 8*j
    uint32_t Wreg[4][4][2];
    #pragma unroll
    for (int ni = 0; ni < 4; ni++) {
        const int c = wn * 32 + ni * 8 + gid;
        #pragma unroll
        for (int kk = 0; kk < 4; kk++)
            #pragma unroll
            for (int j = 0; j < 2; j++) {
                const int k = kk * 16 + 2 * tig + 8 * j;
                Wreg[ni][kk][j] = pack_h2(Ws[k * DC + c], Ws[(k + 1) * DC + c]);
            }
    }

    // ---- A loaders: 2 threads per row, 32 floats each ----
    const int lrow = tid >> 1, lsub = tid & 1;
    const float* aSrc = KB + (size_t)b * ((size_t)DN * DN * DO * DK)
                           + (size_t)(m0 + lrow) * (DN * DO * DK)
                           + (size_t)n0 * (DO * DK) + (size_t)o * DK + lsub * 32;
    const float* xSrc = x + ((size_t)(b * DN + n0) * DO + o) * DC;  // +it*512 per stage
    const uint32_t smem0 = smem_u32(sm);
    const uint32_t aDst0 = smem0 + (uint32_t)lrow * (A_ROWF * 4) + (uint32_t)lsub * 128;
    const uint32_t xBase = smem0 + STAGES * A_STAGE_F * 4;

    auto load_stage = [&](int st) {
        const uint32_t so = (uint32_t)(st % STAGES) * (A_STAGE_F * 4);
        const float* src = aSrc + (size_t)st * (DO * DK);
        const uint32_t d = aDst0 + so;
        #pragma unroll
        for (int j = 0; j < 8; j++) cp16(d + j * 16, src + j * 4);
        if (tid < 32)
            cp16(xBase + (uint32_t)(st % STAGES) * 512 + (uint32_t)tid * 16,
                 xSrc + (size_t)st * (DO * DC) + tid * 4);
    };

    float acc[4][4][4];
    #pragma unroll
    for (int mi = 0; mi < 4; mi++)
        #pragma unroll
        for (int ni = 0; ni < 4; ni++)
            #pragma unroll
            for (int r = 0; r < 4; r++) acc[mi][ni][r] = 0.f;

    // ---- prologue ----
    #pragma unroll
    for (int st = 0; st < STAGES - 1; st++) { load_stage(st); cp_commit(); }

    // ---- mainloop: one source point n (K=64) per iteration ----
    for (int it = 0; it < NITER; it++) {
        cp_wait<STAGES - 2>();   // stage `it` resident
        __syncthreads();
        if (it + STAGES - 1 < NITER) load_stage(it + STAGES - 1);
        cp_commit();

        const float* As = sm + (it % STAGES) * A_STAGE_F;
        const float* xs = sm + STAGES * A_STAGE_F + (it % STAGES) * X_STAGE_F;

        // x broadcast values for this point, one per ni-column
        uint32_t xh2[4];
        #pragma unroll
        for (int ni = 0; ni < 4; ni++) {
            const float xv = xs[wn * 32 + ni * 8 + gid];
            xh2[ni] = pack_h2(xv, xv);
        }

        #pragma unroll
        for (int kk = 0; kk < 4; kk++) {   // K=16 chunks
            uint32_t a[4][4];
            #pragma unroll
            for (int mi = 0; mi < 4; mi++) {
                const float* ap = As + (wm * 64 + mi * 16 + gid) * A_ROWF + kk * 16 + 2 * tig;
                const float2 v00 = *(const float2*)(ap);
                const float2 v10 = *(const float2*)(ap + 8 * A_ROWF);
                const float2 v01 = *(const float2*)(ap + 8);
                const float2 v11 = *(const float2*)(ap + 8 * A_ROWF + 8);
                a[mi][0] = pack_h2(v00.x, v00.y);
                a[mi][1] = pack_h2(v10.x, v10.y);
                a[mi][2] = pack_h2(v01.x, v01.y);
                a[mi][3] = pack_h2(v11.x, v11.y);
            }
            uint32_t bf[4][2];
            #pragma unroll
            for (int ni = 0; ni < 4; ni++) {
                bf[ni][0] = hmul2(xh2[ni], Wreg[ni][kk][0]);
                bf[ni][1] = hmul2(xh2[ni], Wreg[ni][kk][1]);
            }
            #pragma unroll
            for (int mi = 0; mi < 4; mi++)
                #pragma unroll
                for (int ni = 0; ni < 4; ni++)
                    mma_f16(acc[mi][ni][0], acc[mi][ni][1], acc[mi][ni][2], acc[mi][ni][3],
                            a[mi][0], a[mi][1], a[mi][2], a[mi][3],
                            bf[ni][0], bf[ni][1]);
        }
    }

    // ---- epilogue: write partials ----
    #pragma unroll
    for (int mi = 0; mi < 4; mi++) {
        const int row = m0 + wm * 64 + mi * 16 + gid;
        float* y0 = g_Ypart + ((((size_t)s * DB + b) * DN + row) * DO + o) * DC;
        float* y1 = g_Ypart + ((((size_t)s * DB + b) * DN + row + 8) * DO + o) * DC;
        #pragma unroll
        for (int ni = 0; ni < 4; ni++) {
            const int col = wn * 32 + ni * 8 + 2 * tig;
            *(float2*)(y0 + col) = make_float2(acc[mi][ni][0], acc[mi][ni][1]);
            *(float2*)(y1 + col) = make_float2(acc[mi][ni][2], acc[mi][ni][3]);
        }
    }
}

// ---------------- kernel: split-K reduce + fiber rotation + bias ----------------
__global__ void __launch_bounds__(256) sepconv_reduce(const float* __restrict__ bias,
                                                      float* __restrict__ out) {
    const int bm = blockIdx.x * 2 + threadIdx.y;  // 0..767
    const int b = bm / DN, m = bm % DN;
    const int c = threadIdx.x;

    float y[DO];
    #pragma unroll
    for (int o = 0; o < DO; o++) y[o] = 0.f;
    #pragma unroll
    for (int s = 0; s < SPLITS; s++) {
        const float* p = g_Ypart + (((size_t)s * DB + b) * DN + m) * DO * DC + c;
        #pragma unroll
        for (int o = 0; o < DO; o++) y[o] += p[o * DC];
    }
    const float bi = bias[c];
    #pragma unroll
    for (int p = 0; p < DO; p++) {
        float acc = bi;
        #pragma unroll
        for (int o = 0; o < DO; o++) acc += y[o] * g_rot[p][o][c];
        out[(((size_t)b * DN + m) * DO + p) * DC + c] = acc;
    }
}

// ---------------- launcher ----------------
extern "C" void kernel_launch(void* const* d_in, const int* in_sizes, int n_in,
                              void* d_out, int out_size) {
    (void)in_sizes; (void)n_in; (void)out_size;
    const float* x    = (const float*)d_in[0];
    const float* KB   = (const float*)d_in[1];
    const float* fkb  = (const float*)d_in[2];
    const float* Ws   = (const float*)d_in[3];
    const float* Wr   = (const float*)d_in[4];
    const float* bias = (const float*)d_in[5];
    float* out = (float*)d_out;

    static bool attr_done = false;
    if (!attr_done) {
        cudaFuncSetAttribute(sepconv_gemm, cudaFuncAttributeMaxDynamicSharedMemorySize,
                             SMEM_BYTES);
        attr_done = true;
    }

    sepconv_gemm<<<GEMM_CTAS + 1, 256, SMEM_BYTES>>>(KB, x, Ws, fkb, Wr);
    sepconv_reduce<<<DB * DN / 2, dim3(DC, 2)>>>(bias, out);
}